// round 13
// baseline (speedup 1.0000x reference)
#include <cuda_runtime.h>
#include <cuda_bf16.h>
#include <cuda_fp16.h>
#include <cstdint>
#include <math.h>

#define NROWS 16384
#define NHALF 8192
#define DDIM  256
#define NT    128
#define SEGW  8
#define NSEG  1088
#define GT    256
#define GRID_P 152

// ---- device scratch ----
__device__ uint8_t g_q[NROWS * DDIM];     // e4m3 of 16*z_n  (4 MB)
__device__ float  g_pos[NROWS];
__device__ float  g_S[NROWS];
__device__ float  g_corr[NROWS];          // exp(10*(s_ii-1)) diagonal term
__device__ double g_part[64];
__device__ int    g_ticket;
__device__ int    g_done = 0;

// ---- gemm smem: A 32KB + 4 pairs x 2 bufs x 8KB B + ticket ----
#define OFF_A    0
#define OFF_B    32768
#define OFF_BC   98304
#define SMEM_TOTAL 98320

#define C1F 14.42695040888963f        // 10*log2(e)
#define C1S (C1F / 256.0f)            // acc holds 256*sim

// ============================ helpers ============================
__device__ __forceinline__ uint32_t smem_u32(const void* p) {
    uint32_t a;
    asm("{ .reg .u64 t; cvta.to.shared.u64 t, %1; cvt.u32.u64 %0, t; }"
        : "=r"(a) : "l"(p));
    return a;
}
__device__ __forceinline__ void ldsm_x4(uint32_t& r0, uint32_t& r1,
                                        uint32_t& r2, uint32_t& r3,
                                        uint32_t addr) {
    asm volatile("ldmatrix.sync.aligned.m8n8.x4.shared.b16 {%0,%1,%2,%3}, [%4];"
                 : "=r"(r0), "=r"(r1), "=r"(r2), "=r"(r3) : "r"(addr));
}
__device__ __forceinline__ void mma16832(float* d, const uint32_t* a,
                                         uint32_t b0, uint32_t b1) {
    asm volatile(
        "mma.sync.aligned.m16n8k32.row.col.f32.e4m3.e4m3.f32 "
        "{%0,%1,%2,%3}, {%4,%5,%6,%7}, {%8,%9}, {%0,%1,%2,%3};"
        : "+f"(d[0]), "+f"(d[1]), "+f"(d[2]), "+f"(d[3])
        : "r"(a[0]), "r"(a[1]), "r"(a[2]), "r"(a[3]), "r"(b0), "r"(b1));
}
__device__ __forceinline__ float ex2f(float x) {
    float y; asm("ex2.approx.f32 %0, %1;" : "=f"(y) : "f"(x)); return y;
}
__device__ __forceinline__ void cp_commit() {
    asm volatile("cp.async.commit_group;" ::: "memory");
}
template <int N>
__device__ __forceinline__ void cp_wait() {
    asm volatile("cp.async.wait_group %0;" :: "n"(N) : "memory");
}
__device__ __forceinline__ void bar_pair(int id) {
    asm volatile("bar.sync %0, 64;" :: "r"(id) : "memory");
}
// A strip: 128 rows x 256B fp8, full CTA
__device__ __forceinline__ void cp_tile_A(uint32_t sdst, int rowblk, int tid) {
    const char* gp = reinterpret_cast<const char*>(g_q) + (size_t)rowblk * 32768;
    #pragma unroll
    for (int it = 0; it < 8; ++it) {
        int c = tid + it * GT;            // 0..2047 16B chunks
        int r = c >> 4, cc = c & 15;
        uint32_t d = sdst + r * 256 + (((cc ^ (r & 7))) << 4);
        asm volatile("cp.async.cg.shared.global [%0], [%1], 16;"
                     :: "r"(d), "l"(gp + (size_t)c * 16) : "memory");
    }
}
// pair-private B slice: 32 rows x 256B, 64 threads
__device__ __forceinline__ void cp_slice_B(uint32_t sdst, int bj, int wn,
                                           int pairtid) {
    const char* gp = reinterpret_cast<const char*>(g_q)
                     + ((size_t)bj * 128 + wn * 32) * 256;
    #pragma unroll
    for (int it = 0; it < 8; ++it) {
        int c = pairtid + it * 64;        // 0..511 16B chunks
        int r = c >> 4, cc = c & 15;
        uint32_t d = sdst + r * 256 + (((cc ^ (r & 7))) << 4);
        asm volatile("cp.async.cg.shared.global [%0], [%1], 16;"
                     :: "r"(d), "l"(gp + (size_t)c * 16) : "memory");
    }
}

// ============================ K1: normalize + positives + fp8 pack ============================
__global__ void norm_pos_kernel(const float* __restrict__ z1,
                                const float* __restrict__ z2) {
    int r = blockIdx.x;
    int t = threadIdx.x;          // 0..127
    int half = t >> 6, tt = t & 63;
    const float* src = (half ? z2 : z1) + (size_t)r * DDIM;
    float4 v = reinterpret_cast<const float4*>(src)[tt];
    float ss = v.x * v.x + v.y * v.y + v.z * v.z + v.w * v.w;
    #pragma unroll
    for (int o = 16; o; o >>= 1) ss += __shfl_xor_sync(0xffffffffu, ss, o);
    __shared__ float ws[4];
    __shared__ float wq[4];
    __shared__ float sn[2][256];
    if ((t & 31) == 0) ws[t >> 5] = ss;
    __syncthreads();
    float inv = 1.0f / fmaxf(sqrtf(ws[half * 2] + ws[half * 2 + 1]), 1e-6f);
    float4 n;
    n.x = v.x * inv; n.y = v.y * inv; n.z = v.z * inv; n.w = v.w * inv;
    int row = half ? r + NHALF : r;
    // pack 16*z into e4m3
    uint16_t h0, h1;
    asm("cvt.rn.satfinite.e4m3x2.f32 %0, %1, %2;"
        : "=h"(h0) : "f"(n.y * 16.0f), "f"(n.x * 16.0f));
    asm("cvt.rn.satfinite.e4m3x2.f32 %0, %1, %2;"
        : "=h"(h1) : "f"(n.w * 16.0f), "f"(n.z * 16.0f));
    uint32_t w;
    asm("mov.b32 %0, {%1,%2};" : "=r"(w) : "h"(h0), "h"(h1));
    reinterpret_cast<uint32_t*>(g_q + (size_t)row * DDIM)[tt] = w;
    // dequantized self-dot (diagonal correction); e4m3 -> f16 exact
    uint32_t f0, f1;
    asm("cvt.rn.f16x2.e4m3x2 %0, %1;" : "=r"(f0) : "h"(h0));
    asm("cvt.rn.f16x2.e4m3x2 %0, %1;" : "=r"(f1) : "h"(h1));
    float2 q0 = __half22float2(*reinterpret_cast<__half2*>(&f0));
    float2 q1 = __half22float2(*reinterpret_cast<__half2*>(&f1));
    float qq = q0.x * q0.x + q0.y * q0.y + q1.x * q1.x + q1.y * q1.y;
    #pragma unroll
    for (int o = 16; o; o >>= 1) qq += __shfl_xor_sync(0xffffffffu, qq, o);
    if ((t & 31) == 0) wq[t >> 5] = qq;
    reinterpret_cast<float4*>(sn[half])[tt] = n;
    __syncthreads();
    if (tt == 0) {
        float s2 = (wq[half * 2] + wq[half * 2 + 1]) * (1.0f / 256.0f);
        g_corr[row] = ex2f((s2 - 1.0f) * C1F);
    }
    // fp32 positive dot
    float p = sn[0][t * 2] * sn[1][t * 2] + sn[0][t * 2 + 1] * sn[1][t * 2 + 1];
    #pragma unroll
    for (int o = 16; o; o >>= 1) p += __shfl_xor_sync(0xffffffffu, p, o);
    if ((t & 31) == 0) ws[t >> 5] = p;
    __syncthreads();
    if (t == 0) {
        float d = fminf(fmaxf(ws[0] + ws[1] + ws[2] + ws[3], -1.0f + 1e-6f),
                        1.0f - 1e-6f);
        g_pos[r] = d;
        g_pos[r + NHALF] = d;
        g_S[r] = 0.f;
        g_S[r + NHALF] = 0.f;
        if (r == 0) g_ticket = 0;
    }
}

// ===================== K2: persistent symmetric FP8 GEMM + LSE =====================
// Warp layout (R6): wn = wid>>1 (32-col slice), wm = wid&1 (64-row half).
__device__ __forceinline__ void epilogue(float (&acc)[4][4][4],
                                         float (&rsum)[4][2],
                                         int colbase, bool diag, int lane) {
    float csum[4][2];
    #pragma unroll
    for (int nf = 0; nf < 4; ++nf) { csum[nf][0] = 0.f; csum[nf][1] = 0.f; }
    #pragma unroll
    for (int mf = 0; mf < 4; ++mf)
        #pragma unroll
        for (int nf = 0; nf < 4; ++nf)
            #pragma unroll
            for (int e = 0; e < 4; ++e) {
                float ev = ex2f(fmaf(acc[mf][nf][e], C1S, -C1F));
                rsum[mf][e >> 1] += ev;
                csum[nf][e & 1] += ev;
                acc[mf][nf][e] = 0.f;
            }
    if (!diag) {
        const int q = lane & 3;
        #pragma unroll
        for (int nf = 0; nf < 4; ++nf)
            #pragma unroll
            for (int e1 = 0; e1 < 2; ++e1) {
                float v = csum[nf][e1];
                v += __shfl_xor_sync(0xffffffffu, v, 4);
                v += __shfl_xor_sync(0xffffffffu, v, 8);
                v += __shfl_xor_sync(0xffffffffu, v, 16);
                if (lane < 4)
                    atomicAdd(&g_S[colbase + nf * 8 + q * 2 + e1], v);
            }
    }
}

__device__ __forceinline__ void flush_rsum(float (&rsum)[4][2], int bi,
                                           int wm, int lane) {
    const int g = lane >> 2, q = lane & 3;
    #pragma unroll
    for (int mf = 0; mf < 4; ++mf)
        #pragma unroll
        for (int h = 0; h < 2; ++h) {
            float v = rsum[mf][h];
            v += __shfl_xor_sync(0xffffffffu, v, 1);
            v += __shfl_xor_sync(0xffffffffu, v, 2);
            if (q == 0)
                atomicAdd(&g_S[bi * 128 + wm * 64 + mf * 16 + h * 8 + g], v);
            rsum[mf][h] = 0.f;
        }
}

__global__ void __launch_bounds__(GT, 1) gemm_sym_kernel() {
    extern __shared__ char smem[];
    const int tid = threadIdx.x, lane = tid & 31, wid = tid >> 5;
    const int wn = wid >> 1, wm = wid & 1;
    const int pairtid = (wid & 1) * 32 + lane;
    uint32_t sb = smem_u32(smem);
    int* sBC = reinterpret_cast<int*>(smem + OFF_BC);

    // fragment addressing (proven scheme; row stride 256B for fp8)
    const int aRow = lane & 15;
    const int aSel = lane >> 4;
    const int bRowOff = (lane & 7) + ((lane >> 4) << 3);
    const int bSel = (lane >> 3) & 1;
    const int aR7 = aRow & 7, bR7 = bRowOff & 7;
    uint32_t aB[4];
    #pragma unroll
    for (int mf = 0; mf < 4; ++mf)
        aB[mf] = sb + OFF_A + (wm * 64 + mf * 16 + aRow) * 256;
    uint32_t sliceB[2];
    sliceB[0] = sb + OFF_B + wn * 16384;
    sliceB[1] = sliceB[0] + 8192;
    uint32_t bB[2][2];
    #pragma unroll
    for (int bf = 0; bf < 2; ++bf)
        #pragma unroll
        for (int p = 0; p < 2; ++p)
            bB[bf][p] = sliceB[bf] + (p * 16 + bRowOff) * 256;

    float acc[4][4][4];
    #pragma unroll
    for (int mf = 0; mf < 4; ++mf)
        #pragma unroll
        for (int nf = 0; nf < 4; ++nf)
            #pragma unroll
            for (int e = 0; e < 4; ++e) acc[mf][nf][e] = 0.f;
    float rsum[4][2];
    #pragma unroll
    for (int mf = 0; mf < 4; ++mf) { rsum[mf][0] = 0.f; rsum[mf][1] = 0.f; }

    const int barid = 1 + wn;
    int cur_bi = -1;

    for (;;) {
        if (tid == 0) sBC[0] = atomicAdd(&g_ticket, 1);
        __syncthreads();
        int c = sBC[0];
        if (c >= NSEG) break;

        int idx = c, bi = 0;
        for (;;) {
            int ns = (NT - bi + SEGW - 1) >> 3;
            if (idx < ns) break;
            idx -= ns; ++bi;
        }
        const int j0 = bi + idx * SEGW;
        const int len = min(SEGW, NT - j0);
        const bool reloadA = (bi != cur_bi);

        if (reloadA) {
            if (cur_bi >= 0) flush_rsum(rsum, cur_bi, wm, lane);
            cp_tile_A(sb + OFF_A, bi, tid);
            cp_commit();            // <<< FIX: A gets its own group (R6 accounting)
            cur_bi = bi;
        }
        cp_slice_B(sliceB[0], j0, wn, pairtid);
        cp_commit();
        if (len > 1) {
            cp_slice_B(sliceB[1], j0 + 1, wn, pairtid);
            cp_commit();
        }
        if (reloadA) {
            // retire A, then make it visible CTA-wide
            if (len > 1) cp_wait<2>(); else cp_wait<1>();
            __syncthreads();
        }

        for (int t = 0; t < len; ++t) {
            const int buf = t & 1;
            if (t < len - 1) cp_wait<1>(); else cp_wait<0>();
            bar_pair(barid);                 // pair's B(t) visible

            // ---- MMA over K = 256 fp8 (8 k32 steps) ----
            #pragma unroll
            for (int kk = 0; kk < 8; ++kk) {
                uint32_t a[4][4], b[2][4];
                uint32_t aoff = (uint32_t)(((2 * kk + aSel) ^ aR7) << 4);
                #pragma unroll
                for (int mf = 0; mf < 4; ++mf)
                    ldsm_x4(a[mf][0], a[mf][1], a[mf][2], a[mf][3],
                            aB[mf] + aoff);
                uint32_t boff = (uint32_t)(((2 * kk + bSel) ^ bR7) << 4);
                ldsm_x4(b[0][0], b[0][1], b[0][2], b[0][3], bB[buf][0] + boff);
                ldsm_x4(b[1][0], b[1][1], b[1][2], b[1][3], bB[buf][1] + boff);
                #pragma unroll
                for (int mf = 0; mf < 4; ++mf)
                    #pragma unroll
                    for (int nf = 0; nf < 4; ++nf)
                        mma16832(acc[mf][nf], a[mf],
                                 b[nf >> 1][(nf & 1) * 2],
                                 b[nf >> 1][(nf & 1) * 2 + 1]);
            }
            bar_pair(barid);                 // both warps done reading buf
            if (t + 2 < len) {
                cp_slice_B(sliceB[buf], j0 + t + 2, wn, pairtid);
                cp_commit();
            }

            // ---- uniform epilogue (no masking; diag handled by g_corr) ----
            const int bj = j0 + t;
            epilogue(acc, rsum, bj * 128 + wn * 32, bj == bi, lane);
        }
    }

    if (cur_bi >= 0) flush_rsum(rsum, cur_bi, wm, lane);
}

// ============================ K3: loss ============================
__global__ void loss_kernel(float* __restrict__ out) {
    int r = blockIdx.x * 256 + threadIdx.x;
    float S = g_S[r] - g_corr[r];          // remove diagonal term
    double v = (double)logf(S) + 10.0 - 10.0 * (double)g_pos[r];
    #pragma unroll
    for (int o = 16; o; o >>= 1) v += __shfl_xor_sync(0xffffffffu, v, o);
    __shared__ double sd[8];
    if ((threadIdx.x & 31) == 0) sd[threadIdx.x >> 5] = v;
    __syncthreads();
    if (threadIdx.x == 0) {
        double a = 0.0;
        #pragma unroll
        for (int i = 0; i < 8; ++i) a += sd[i];
        g_part[blockIdx.x] = a;
        __threadfence();
        int n = atomicAdd(&g_done, 1);
        if (n == 63) {
            __threadfence();
            double s = 0.0;
            for (int i = 0; i < 64; ++i)
                s += *((volatile double*)&g_part[i]);
            out[0] = (float)(s / (double)NROWS);
            g_done = 0;
        }
    }
}

// ---------------------------------------------------------------------------
extern "C" void kernel_launch(void* const* d_in, const int* in_sizes, int n_in,
                              void* d_out, int out_size) {
    (void)in_sizes; (void)n_in; (void)out_size;
    const float* z1 = (const float*)d_in[0];
    const float* z2 = (const float*)d_in[1];
    float* out = (float*)d_out;

    cudaFuncSetAttribute(gemm_sym_kernel,
                         cudaFuncAttributeMaxDynamicSharedMemorySize, SMEM_TOTAL);

    norm_pos_kernel<<<NHALF, 128>>>(z1, z2);
    gemm_sym_kernel<<<GRID_P, GT, SMEM_TOTAL>>>();
    loss_kernel<<<64, 256>>>(out);
}

// round 14
// speedup vs baseline: 1.8179x; 1.8179x over previous
#include <cuda_runtime.h>
#include <cuda_bf16.h>
#include <cuda_fp16.h>
#include <cstdint>
#include <math.h>

#define NROWS 16384
#define NHALF 8192
#define DDIM  256
#define NT    128
#define SEGW  8
#define NSEG  1088
#define GT    256
#define GRID_P 152

// ---- device scratch ----
__device__ __nv_bfloat16 g_zn[NROWS * DDIM];
__device__ float  g_pos[NROWS];
__device__ float  g_S[NROWS];          // scaled by 1024
__device__ double g_part[64];
__device__ int    g_ticket;
__device__ int    g_done = 0;

// ---- gemm smem: A 64KB, then 4 pairs x 2 bufs x 16KB B slices ----
#define OFF_A    0
#define OFF_B    65536
#define OFF_BC   196608
#define SMEM_TOTAL 196624

#define C1F 14.42695040888963f    // 10*log2(e)
#define B10 (-C1F + 10.0f)        // bias: compute 1024*exp(10*sim-10)
#define LN2_10 6.931471805599453  // 10*ln(2), removes the 1024 scale

// ============================ helpers ============================
__device__ __forceinline__ uint32_t smem_u32(const void* p) {
    uint32_t a;
    asm("{ .reg .u64 t; cvta.to.shared.u64 t, %1; cvt.u32.u64 %0, t; }"
        : "=r"(a) : "l"(p));
    return a;
}
__device__ __forceinline__ void ldsm_x4(uint32_t& r0, uint32_t& r1,
                                        uint32_t& r2, uint32_t& r3,
                                        uint32_t addr) {
    asm volatile("ldmatrix.sync.aligned.m8n8.x4.shared.b16 {%0,%1,%2,%3}, [%4];"
                 : "=r"(r0), "=r"(r1), "=r"(r2), "=r"(r3) : "r"(addr));
}
__device__ __forceinline__ void mma16816(float* d, const uint32_t* a,
                                         uint32_t b0, uint32_t b1) {
    asm volatile(
        "mma.sync.aligned.m16n8k16.row.col.f32.bf16.bf16.f32 "
        "{%0,%1,%2,%3}, {%4,%5,%6,%7}, {%8,%9}, {%0,%1,%2,%3};"
        : "+f"(d[0]), "+f"(d[1]), "+f"(d[2]), "+f"(d[3])
        : "r"(a[0]), "r"(a[1]), "r"(a[2]), "r"(a[3]), "r"(b0), "r"(b1));
}
__device__ __forceinline__ half2 h2ex2(half2 x) {
    half2 y;
    asm("ex2.approx.f16x2 %0, %1;" : "=r"(*reinterpret_cast<uint32_t*>(&y))
        : "r"(*reinterpret_cast<const uint32_t*>(&x)));
    return y;
}
__device__ __forceinline__ void cp_commit() {
    asm volatile("cp.async.commit_group;" ::: "memory");
}
template <int N>
__device__ __forceinline__ void cp_wait() {
    asm volatile("cp.async.wait_group %0;" :: "n"(N) : "memory");
}
__device__ __forceinline__ void bar_pair(int id) {
    asm volatile("bar.sync %0, 64;" :: "r"(id) : "memory");
}
__device__ __forceinline__ void cp_tile_A(uint32_t sdst, int rowblk, int tid) {
    const char* gp = reinterpret_cast<const char*>(g_zn) + (size_t)rowblk * 65536;
    #pragma unroll
    for (int it = 0; it < 16; ++it) {
        int c = tid + it * GT;
        int r = c >> 5, cc = c & 31;
        uint32_t d = sdst + r * 512 + (((cc ^ (r & 7))) << 4);
        asm volatile("cp.async.cg.shared.global [%0], [%1], 16;"
                     :: "r"(d), "l"(gp + (size_t)c * 16) : "memory");
    }
}
__device__ __forceinline__ void cp_slice_B(uint32_t sdst, int bj, int wn,
                                           int pairtid) {
    const char* gp = reinterpret_cast<const char*>(g_zn)
                     + ((size_t)bj * 128 + wn * 32) * 512;
    #pragma unroll
    for (int it = 0; it < 16; ++it) {
        int c = pairtid + it * 64;
        int r = c >> 5, cc = c & 31;
        uint32_t d = sdst + r * 512 + (((cc ^ (r & 7))) << 4);
        asm volatile("cp.async.cg.shared.global [%0], [%1], 16;"
                     :: "r"(d), "l"(gp + (size_t)c * 16) : "memory");
    }
}

// ============================ K1: normalize + positives ============================
__global__ void norm_pos_kernel(const float* __restrict__ z1,
                                const float* __restrict__ z2) {
    int r = blockIdx.x;
    int t = threadIdx.x;
    int half_ = t >> 6, tt = t & 63;
    const float* src = (half_ ? z2 : z1) + (size_t)r * DDIM;
    float4 v = reinterpret_cast<const float4*>(src)[tt];
    float ss = v.x * v.x + v.y * v.y + v.z * v.z + v.w * v.w;
    #pragma unroll
    for (int o = 16; o; o >>= 1) ss += __shfl_xor_sync(0xffffffffu, ss, o);
    __shared__ float ws[4];
    __shared__ float sn[2][256];
    if ((t & 31) == 0) ws[t >> 5] = ss;
    __syncthreads();
    float inv = 1.0f / fmaxf(sqrtf(ws[half_ * 2] + ws[half_ * 2 + 1]), 1e-6f);
    float4 n;
    n.x = v.x * inv; n.y = v.y * inv; n.z = v.z * inv; n.w = v.w * inv;
    __nv_bfloat162 h0 = __floats2bfloat162_rn(n.x, n.y);
    __nv_bfloat162 h1 = __floats2bfloat162_rn(n.z, n.w);
    uint2 packed;
    packed.x = *reinterpret_cast<uint32_t*>(&h0);
    packed.y = *reinterpret_cast<uint32_t*>(&h1);
    int row = half_ ? r + NHALF : r;
    reinterpret_cast<uint2*>(g_zn + (size_t)row * DDIM)[tt] = packed;
    reinterpret_cast<float4*>(sn[half_])[tt] = n;
    __syncthreads();
    float p = sn[0][t * 2] * sn[1][t * 2] + sn[0][t * 2 + 1] * sn[1][t * 2 + 1];
    #pragma unroll
    for (int o = 16; o; o >>= 1) p += __shfl_xor_sync(0xffffffffu, p, o);
    if ((t & 31) == 0) ws[t >> 5] = p;
    __syncthreads();
    if (t == 0) {
        float d = fminf(fmaxf(ws[0] + ws[1] + ws[2] + ws[3], -1.0f + 1e-6f),
                        1.0f - 1e-6f);
        g_pos[r] = d;
        g_pos[r + NHALF] = d;
        g_S[r] = 0.f;
        g_S[r + NHALF] = 0.f;
        if (r == 0) g_ticket = 0;
    }
}

// ===================== K2: persistent symmetric GEMM + LSE =====================
// Warp layout (R6, verified): wn = wid>>1 (32-col slice 0..3), wm = wid&1.
// Epilogue in packed f16: 1024*exp(10*sim-10), h2exp2 halves MUFU work.
template <bool MASK>
__device__ __forceinline__ void epilogue(float (&acc)[4][4][4],
                                         float (&rsum)[4][2],
                                         int colbase, int lane,
                                         const uint32_t* dd) {
    half2 hrs[4][2];
    half2 hcs[4];
    const half2 hz = __floats2half2_rn(0.f, 0.f);
    #pragma unroll
    for (int mf = 0; mf < 4; ++mf) { hrs[mf][0] = hz; hrs[mf][1] = hz; }
    #pragma unroll
    for (int nf = 0; nf < 4; ++nf) hcs[nf] = hz;

    #pragma unroll
    for (int mf = 0; mf < 4; ++mf)
        #pragma unroll
        for (int nf = 0; nf < 4; ++nf) {
            float y0 = fmaf(acc[mf][nf][0], C1F, B10);
            float y1 = fmaf(acc[mf][nf][1], C1F, B10);
            float y2 = fmaf(acc[mf][nf][2], C1F, B10);
            float y3 = fmaf(acc[mf][nf][3], C1F, B10);
            if (MASK) {
                const uint32_t kk = (uint32_t)((mf * 4 + nf) << 2);
                if (kk + 0 == dd[0] || kk + 0 == dd[1] ||
                    kk + 0 == dd[2] || kk + 0 == dd[3]) y0 = -1000.f;
                if (kk + 1 == dd[0] || kk + 1 == dd[1] ||
                    kk + 1 == dd[2] || kk + 1 == dd[3]) y1 = -1000.f;
                if (kk + 2 == dd[0] || kk + 2 == dd[1] ||
                    kk + 2 == dd[2] || kk + 2 == dd[3]) y2 = -1000.f;
                if (kk + 3 == dd[0] || kk + 3 == dd[1] ||
                    kk + 3 == dd[2] || kk + 3 == dd[3]) y3 = -1000.f;
            }
            half2 p0 = h2ex2(__floats2half2_rn(y0, y1));
            half2 p1 = h2ex2(__floats2half2_rn(y2, y3));
            hrs[mf][0] = __hadd2(hrs[mf][0], p0);
            hrs[mf][1] = __hadd2(hrs[mf][1], p1);
            hcs[nf] = __hadd2(hcs[nf], __hadd2(p0, p1));
            acc[mf][nf][0] = 0.f; acc[mf][nf][1] = 0.f;
            acc[mf][nf][2] = 0.f; acc[mf][nf][3] = 0.f;
        }

    // fold row sums into f32 (persist across tiles)
    #pragma unroll
    for (int mf = 0; mf < 4; ++mf)
        #pragma unroll
        for (int h = 0; h < 2; ++h) {
            float2 f = __half22float2(hrs[mf][h]);
            rsum[mf][h] += f.x + f.y;
        }

    // column sums: half2 butterfly then direct RED (skip on diag tiles)
    if (!MASK) {
        const int q = lane & 3;
        #pragma unroll
        for (int nf = 0; nf < 4; ++nf) {
            uint32_t v = *reinterpret_cast<uint32_t*>(&hcs[nf]);
            uint32_t w;
            w = __shfl_xor_sync(0xffffffffu, v, 4);
            hcs[nf] = __hadd2(hcs[nf], *reinterpret_cast<half2*>(&w));
            v = *reinterpret_cast<uint32_t*>(&hcs[nf]);
            w = __shfl_xor_sync(0xffffffffu, v, 8);
            hcs[nf] = __hadd2(hcs[nf], *reinterpret_cast<half2*>(&w));
            v = *reinterpret_cast<uint32_t*>(&hcs[nf]);
            w = __shfl_xor_sync(0xffffffffu, v, 16);
            hcs[nf] = __hadd2(hcs[nf], *reinterpret_cast<half2*>(&w));
            if (lane < 4) {
                float2 f = __half22float2(hcs[nf]);
                atomicAdd(&g_S[colbase + nf * 8 + q * 2 + 0], f.x);
                atomicAdd(&g_S[colbase + nf * 8 + q * 2 + 1], f.y);
            }
        }
    }
}

__device__ __forceinline__ void flush_rsum(float (&rsum)[4][2], int bi,
                                           int wm, int lane) {
    const int g = lane >> 2, q = lane & 3;
    #pragma unroll
    for (int mf = 0; mf < 4; ++mf)
        #pragma unroll
        for (int h = 0; h < 2; ++h) {
            float v = rsum[mf][h];
            v += __shfl_xor_sync(0xffffffffu, v, 1);
            v += __shfl_xor_sync(0xffffffffu, v, 2);
            if (q == 0)
                atomicAdd(&g_S[bi * 128 + wm * 64 + mf * 16 + h * 8 + g], v);
            rsum[mf][h] = 0.f;
        }
}

__global__ void __launch_bounds__(GT, 1) gemm_sym_kernel() {
    extern __shared__ char smem[];
    const int tid = threadIdx.x, lane = tid & 31, wid = tid >> 5;
    const int wn = wid >> 1, wm = wid & 1;
    const int pairtid = (wid & 1) * 32 + lane;
    const int g = lane >> 2, q = lane & 3;
    uint32_t sb = smem_u32(smem);
    int* sBC = reinterpret_cast<int*>(smem + OFF_BC);

    // fragment addressing (R6, verified)
    const int aRow = lane & 15;
    const int aSel = lane >> 4;
    const int bRowOff = (lane & 7) + ((lane >> 4) << 3);
    const int bSel = (lane >> 3) & 1;
    const int aR7 = aRow & 7, bR7 = bRowOff & 7;
    uint32_t aB[4];
    #pragma unroll
    for (int mf = 0; mf < 4; ++mf)
        aB[mf] = sb + OFF_A + (wm * 64 + mf * 16 + aRow) * 512;
    uint32_t sliceB[2];
    sliceB[0] = sb + OFF_B + (wn * 2) * 16384;
    sliceB[1] = sliceB[0] + 16384;
    uint32_t bB[2][2];
    #pragma unroll
    for (int bf = 0; bf < 2; ++bf)
        #pragma unroll
        for (int p = 0; p < 2; ++p)
            bB[bf][p] = sliceB[bf] + (p * 16 + bRowOff) * 512;

    // diag element ids (R6, verified rel_err 0)
    const bool qual = ((wn >> 1) == wm) && (q == (g >> 1));
    const int e1b = g & 1;
    uint32_t dd[4];
    {
        int base = (wn & 1) * 4;
        #pragma unroll
        for (int k = 0; k < 4; ++k) {
            int mf = base ? (2 + (k >> 1)) : (k >> 1);
            int e2 = k & 1;
            int nf = mf * 2 + e2 - (base ? 4 : 0);
            dd[k] = qual ? (uint32_t)(((mf * 4 + nf) << 2) + e2 * 2 + e1b) : 255u;
        }
    }

    float acc[4][4][4];
    #pragma unroll
    for (int mf = 0; mf < 4; ++mf)
        #pragma unroll
        for (int nf = 0; nf < 4; ++nf)
            #pragma unroll
            for (int e = 0; e < 4; ++e) acc[mf][nf][e] = 0.f;
    float rsum[4][2];
    #pragma unroll
    for (int mf = 0; mf < 4; ++mf) { rsum[mf][0] = 0.f; rsum[mf][1] = 0.f; }

    const int barid = 1 + wn;
    int cur_bi = -1;

    for (;;) {
        if (tid == 0) sBC[0] = atomicAdd(&g_ticket, 1);
        __syncthreads();
        int c = sBC[0];
        if (c >= NSEG) break;

        int idx = c, bi = 0;
        for (;;) {
            int ns = (NT - bi + SEGW - 1) >> 3;
            if (idx < ns) break;
            idx -= ns; ++bi;
        }
        const int j0 = bi + idx * SEGW;
        const int len = min(SEGW, NT - j0);
        const bool reloadA = (bi != cur_bi);

        if (reloadA) {
            if (cur_bi >= 0) flush_rsum(rsum, cur_bi, wm, lane);
            cp_tile_A(sb + OFF_A, bi, tid);
            cp_commit();
            cur_bi = bi;
        }
        cp_slice_B(sliceB[0], j0, wn, pairtid);
        cp_commit();
        if (len > 1) {
            cp_slice_B(sliceB[1], j0 + 1, wn, pairtid);
            cp_commit();
        }
        if (reloadA) {
            if (len > 1) cp_wait<2>(); else cp_wait<1>();
            __syncthreads();
        }

        for (int t = 0; t < len; ++t) {
            const int buf = t & 1;
            if (t < len - 1) cp_wait<1>(); else cp_wait<0>();
            bar_pair(barid);                 // pair's B(t) visible

            // ---- MMA over K = 256 ----
            #pragma unroll
            for (int kk = 0; kk < 16; ++kk) {
                uint32_t a[4][4], b[2][4];
                uint32_t aoff = (uint32_t)(((2 * kk + aSel) ^ aR7) << 4);
                #pragma unroll
                for (int mf = 0; mf < 4; ++mf)
                    ldsm_x4(a[mf][0], a[mf][1], a[mf][2], a[mf][3],
                            aB[mf] + aoff);
                uint32_t boff = (uint32_t)(((2 * kk + bSel) ^ bR7) << 4);
                ldsm_x4(b[0][0], b[0][1], b[0][2], b[0][3], bB[buf][0] + boff);
                ldsm_x4(b[1][0], b[1][1], b[1][2], b[1][3], bB[buf][1] + boff);
                #pragma unroll
                for (int mf = 0; mf < 4; ++mf)
                    #pragma unroll
                    for (int nf = 0; nf < 4; ++nf)
                        mma16816(acc[mf][nf], a[mf],
                                 b[nf >> 1][(nf & 1) * 2],
                                 b[nf >> 1][(nf & 1) * 2 + 1]);
            }
            bar_pair(barid);                 // both warps done reading buf
            if (t + 2 < len) {
                cp_slice_B(sliceB[buf], j0 + t + 2, wn, pairtid);
                cp_commit();
            }

            // ---- packed f16 epilogue ----
            const int bj = j0 + t;
            if (bj == bi)
                epilogue<true >(acc, rsum, 0, lane, dd);
            else
                epilogue<false>(acc, rsum, bj * 128 + wn * 32, lane, dd);
        }
    }

    if (cur_bi >= 0) flush_rsum(rsum, cur_bi, wm, lane);
}

// ============================ K3: loss ============================
__global__ void loss_kernel(float* __restrict__ out) {
    int r = blockIdx.x * 256 + threadIdx.x;
    // g_S holds 1024*S; log(S) = log(g_S) - 10*ln2
    double v = (double)logf(g_S[r]) - LN2_10 + 10.0 - 10.0 * (double)g_pos[r];
    #pragma unroll
    for (int o = 16; o; o >>= 1) v += __shfl_xor_sync(0xffffffffu, v, o);
    __shared__ double sd[8];
    if ((threadIdx.x & 31) == 0) sd[threadIdx.x >> 5] = v;
    __syncthreads();
    if (threadIdx.x == 0) {
        double a = 0.0;
        #pragma unroll
        for (int i = 0; i < 8; ++i) a += sd[i];
        g_part[blockIdx.x] = a;
        __threadfence();
        int n = atomicAdd(&g_done, 1);
        if (n == 63) {
            __threadfence();
            double s = 0.0;
            for (int i = 0; i < 64; ++i)
                s += *((volatile double*)&g_part[i]);
            out[0] = (float)(s / (double)NROWS);
            g_done = 0;
        }
    }
}

// ---------------------------------------------------------------------------
extern "C" void kernel_launch(void* const* d_in, const int* in_sizes, int n_in,
                              void* d_out, int out_size) {
    (void)in_sizes; (void)n_in; (void)out_size;
    const float* z1 = (const float*)d_in[0];
    const float* z2 = (const float*)d_in[1];
    float* out = (float*)d_out;

    cudaFuncSetAttribute(gemm_sym_kernel,
                         cudaFuncAttributeMaxDynamicSharedMemorySize, SMEM_TOTAL);

    norm_pos_kernel<<<NHALF, 128>>>(z1, z2);
    gemm_sym_kernel<<<GRID_P, GT, SMEM_TOTAL>>>();
    loss_kernel<<<64, 256>>>(out);
}